// round 16
// baseline (speedup 1.0000x reference)
#include <cuda_runtime.h>
#include <cuda_fp16.h>
#include <cuda_bf16.h>
#include <math.h>
#include <stdint.h>
#include <stddef.h>

#define DIM   128
#define NN    20000
#define NNZV  500000
#define EE    5000
#define CC    50
#define NENT  50000
#define NKEY  60000
#define NHEAD 8
#define DH    16

#define NN_PAD   20096      // 314 * 64
#define NKEY_PAD 60032      // 938 * 64
#define NT64_NN   314
#define NT64_NKEY 938
#define TPCX 2              // A-tiles per CTA (xt GEMM)
#define TPC  4              // A-tiles per CTA (K/V GEMM)

#define FP8_SCALE 16.0f

// ===================== helpers ==============================================
__device__ __forceinline__ uint32_t smem_u32(const void* p) {
    uint32_t a;
    asm("{ .reg .u64 t; cvta.to.shared.u64 t, %1; cvt.u32.u64 %0, t; }"
        : "=r"(a) : "l"(p));
    return a;
}
__device__ __forceinline__ void ldsm4(uint32_t& r0, uint32_t& r1,
                                      uint32_t& r2, uint32_t& r3, uint32_t addr) {
    asm volatile("ldmatrix.sync.aligned.m8n8.x4.shared.b16 {%0,%1,%2,%3}, [%4];"
                 : "=r"(r0), "=r"(r1), "=r"(r2), "=r"(r3) : "r"(addr));
}
__device__ __forceinline__ void mma16816(float* c,
        uint32_t a0, uint32_t a1, uint32_t a2, uint32_t a3,
        uint32_t b0, uint32_t b1) {
    asm volatile("mma.sync.aligned.m16n8k16.row.col.f32.bf16.bf16.f32 "
                 "{%0,%1,%2,%3}, {%4,%5,%6,%7}, {%8,%9}, {%0,%1,%2,%3};"
                 : "+f"(c[0]), "+f"(c[1]), "+f"(c[2]), "+f"(c[3])
                 : "r"(a0), "r"(a1), "r"(a2), "r"(a3), "r"(b0), "r"(b1));
}
__device__ __forceinline__ void cp_async16(uint32_t s, const void* g) {
    asm volatile("cp.async.cg.shared.global [%0], [%1], 16;" :: "r"(s), "l"(g));
}
#define CP_COMMIT() asm volatile("cp.async.commit_group;" ::: "memory")
#define CP_WAIT0()  asm volatile("cp.async.wait_group 0;" ::: "memory")
__device__ __forceinline__ uint16_t f32x2_to_e4m3x2(float hi, float lo) {
    uint16_t r;
    asm("cvt.rn.satfinite.e4m3x2.f32 %0, %1, %2;" : "=h"(r) : "f"(hi), "f"(lo));
    return r;
}
__device__ __forceinline__ float2 e4m3x2_to_f32x2(uint16_t v) {
    uint32_t h2;
    asm("cvt.rn.f16x2.e4m3x2 %0, %1;" : "=r"(h2) : "h"(v));
    return __half22float2(*(__half2*)&h2);
}
__device__ __forceinline__ float fast_exp(float x) {
    if (fabsf(x) > 1.0f) return __expf(x);
    float p = 1.3888889e-3f;
    p = fmaf(p, x, 8.3333333e-3f);
    p = fmaf(p, x, 4.1666667e-2f);
    p = fmaf(p, x, 1.6666667e-1f);
    p = fmaf(p, x, 0.5f);
    p = fmaf(p, x, 1.0f);
    p = fmaf(p, x, 1.0f);
    return p;
}

// ===================== scratch =============================================
__device__ __align__(16) __nv_bfloat16 d_xtA[3 * NN_PAD * DIM];
__device__ __align__(16) __nv_bfloat16 d_relb[NKEY_PAD * DIM];
__device__ __align__(16) __nv_bfloat16 d_WT[5][DIM * DIM];       // W^T [n][k]
__device__ __align__(16) uint8_t d_xt8[3 * NN * DIM];            // fp8 x16
__device__ __align__(16) uint8_t d_me8[3 * EE * DIM];            // fp8 x16
__device__ __align__(16) __nv_bfloat16 d_Kbh[NKEY * DIM];
__device__ __align__(16) __nv_bfloat16 d_Vbh[NKEY * DIM];
__device__ float d_qb  [CC * DIM];
__device__ float d_lsum[NHEAD * CC];
__device__ float d_headout[CC * DIM];
__device__ float d_att [CC * DIM];
__device__ float d_es1[CC];
__device__ float d_es2[CC];
__device__ float d_urepr[DIM];

__device__ int d_ecnt[3 * EE];
__device__ int d_eoff[3 * (EE + 1)];
__device__ int d_ecur[3 * EE];
__device__ int d_ncnt[3 * NN];
__device__ int d_noff[3 * (NN + 1)];
__device__ int d_ncur[3 * NN];
__device__ int d_csrE[3 * NNZV];
__device__ int d_csrN[3 * NNZV];

// ===================== init =================================================
__global__ void zero_kernel() {
    int i = blockIdx.x * blockDim.x + threadIdx.x;
    if (i < 3 * EE)       d_ecnt[i] = 0;
    if (i < 3 * NN)       d_ncnt[i] = 0;
    if (i < CC * DIM)     d_headout[i] = 0.f;
    if (i < NHEAD * CC)   d_lsum[i] = 0.f;
    if (i < (NKEY_PAD - NKEY) * DIM / 2)
        ((unsigned*)d_relb)[(size_t)NKEY * DIM / 2 + i] = 0u;
}

// ===================== weight pre-convert ===================================
__global__ void convW_kernel(const float* __restrict__ w0, const float* __restrict__ w1,
                             const float* __restrict__ w2, const float* __restrict__ w3,
                             const float* __restrict__ w4) {
    const float* W = (blockIdx.x == 0) ? w0 : (blockIdx.x == 1) ? w1 :
                     (blockIdx.x == 2) ? w2 : (blockIdx.x == 3) ? w3 : w4;
    __nv_bfloat16* out = d_WT[blockIdx.x];
    int n = threadIdx.x;
    int k0 = blockIdx.y * 16;
    __nv_bfloat16 tmp[16];
#pragma unroll
    for (int kk = 0; kk < 16; kk++)
        tmp[kk] = __float2bfloat16(W[(size_t)(k0 + kk) * DIM + n]);
    uint4* dst = (uint4*)&out[(size_t)n * DIM + k0];
    dst[0] = ((uint4*)tmp)[0];
    dst[1] = ((uint4*)tmp)[1];
}

// ===================== A pre-convert ========================================
__global__ void convA_kernel(const float* __restrict__ a0, const float* __restrict__ a1,
                             const float* __restrict__ a2) {
    int gid = blockIdx.x * blockDim.x + threadIdx.x;
    if (gid >= 3 * NN_PAD * 16) return;
    int row = gid >> 4, cg = gid & 15;
    int mod = row / NN_PAD, r = row - mod * NN_PAD;
    __nv_bfloat162 h[4];
    if (r < NN) {
        const float* src = ((mod == 0) ? a0 : (mod == 1) ? a1 : a2) + (size_t)r * DIM + cg * 8;
        float4 v0 = *(const float4*)src;
        float4 v1 = *(const float4*)(src + 4);
        h[0] = __floats2bfloat162_rn(v0.x, v0.y);
        h[1] = __floats2bfloat162_rn(v0.z, v0.w);
        h[2] = __floats2bfloat162_rn(v1.x, v1.y);
        h[3] = __floats2bfloat162_rn(v1.z, v1.w);
    } else {
        h[0] = h[1] = h[2] = h[3] = __floats2bfloat162_rn(0.f, 0.f);
    }
    *(uint4*)((char*)d_xtA + (size_t)gid * 16) = *(uint4*)h;
}

// ===================== GEMM core ============================================
#define TS 136
__device__ __forceinline__ void load_a_tile_async(uint32_t abuf,
        const __nv_bfloat16* A, int tile, int tid) {
    const uint4* src = (const uint4*)(A + (size_t)tile * 64 * DIM);
#pragma unroll
    for (int i = 0; i < 4; i++) {
        int c = tid + i * 256;
        int r = c >> 4, kq = c & 15;
        cp_async16(abuf + (uint32_t)((r * TS + kq * 8) * 2), src + c);
    }
}

// ---- xt GEMM: grid (ceil(NT64_NN/TPCX), 3); fp8 out ------------------------
__global__ __launch_bounds__(256, 2)
void mmagemm_x() {
    __shared__ __align__(16) __nv_bfloat16 As[2][64 * TS];
    __shared__ __align__(16) __nv_bfloat16 Ws[128 * TS];
    int y = blockIdx.y;
    int tid = threadIdx.x, wid = tid >> 5, lane = tid & 31;
    const __nv_bfloat16* A = d_xtA + (size_t)y * NN_PAD * DIM;
    uint8_t* Cout = d_xt8 + (size_t)y * NN * DIM;
    {
        const uint4* src = (const uint4*)d_WT[y];
        for (int c = tid; c < 2048; c += 256) {
            int n = c >> 4, kq = c & 15;
            *(uint4*)&Ws[n * TS + kq * 8] = src[c];
        }
    }
    int rg = wid >> 1, nh = wid & 1;
    uint32_t ab0 = smem_u32(As[0]), ab1 = smem_u32(As[1]);
    uint32_t wbase = smem_u32(Ws);
    int nofs = (lane & 7) + ((lane >> 4) << 3);
    int kofs = lane & 8;
    int arow = rg * 16 + (lane & 15);
    int akof = (lane >> 4) << 3;
    int g = lane >> 2, t2 = (lane & 3) * 2;

    int tile0 = blockIdx.x * TPCX;
    int tmax = NT64_NN - tile0; if (tmax > TPCX) tmax = TPCX;
    if (tmax <= 0) return;
    load_a_tile_async(ab0, A, tile0, tid);
    CP_COMMIT(); CP_WAIT0();
    __syncthreads();

    for (int t = 0; t < tmax; t++) {
        uint32_t abase = (t & 1) ? ab1 : ab0;
        if (t + 1 < tmax) {
            load_a_tile_async((t & 1) ? ab0 : ab1, A, tile0 + t + 1, tid);
            CP_COMMIT();
        }
        float acc[8][4];
#pragma unroll
        for (int i = 0; i < 8; i++)
#pragma unroll
            for (int j = 0; j < 4; j++) acc[i][j] = 0.f;
#pragma unroll
        for (int kc = 0; kc < 8; kc++) {
            int k0 = kc * 16;
            uint32_t a0, a1, a2, a3;
            ldsm4(a0, a1, a2, a3, abase + (uint32_t)((arow * TS + k0 + akof) * 2));
#pragma unroll
            for (int nb = 0; nb < 4; nb++) {
                uint32_t b0, b1, b2, b3;
                ldsm4(b0, b1, b2, b3, wbase +
                      (uint32_t)(((nh * 64 + nb * 16 + nofs) * TS + k0 + kofs) * 2));
                mma16816(acc[nb * 2],     a0, a1, a2, a3, b0, b1);
                mma16816(acc[nb * 2 + 1], a0, a1, a2, a3, b2, b3);
            }
        }
        int row0 = (tile0 + t) * 64 + rg * 16 + g, row1 = row0 + 8;
#pragma unroll
        for (int nc = 0; nc < 8; nc++) {
            int col = nh * 64 + nc * 8 + t2;
            if (row0 < NN)
                *(uint16_t*)(Cout + (size_t)row0 * DIM + col) =
                    f32x2_to_e4m3x2(acc[nc][1] * FP8_SCALE, acc[nc][0] * FP8_SCALE);
            if (row1 < NN)
                *(uint16_t*)(Cout + (size_t)row1 * DIM + col) =
                    f32x2_to_e4m3x2(acc[nc][3] * FP8_SCALE, acc[nc][2] * FP8_SCALE);
        }
        CP_WAIT0();
        __syncthreads();
    }
}

// ---- K/V GEMM: grid (ceil(NT64_NKEY/TPC), 2); bf16 out + bias --------------
__global__ __launch_bounds__(256, 2)
void mmagemm_kv(const float* __restrict__ bk, const float* __restrict__ bv) {
    __shared__ __align__(16) __nv_bfloat16 As[2][64 * TS];
    __shared__ __align__(16) __nv_bfloat16 Ws[128 * TS];
    __shared__ float bias_s[128];
    int y = blockIdx.y;
    int tid = threadIdx.x, wid = tid >> 5, lane = tid & 31;
    __nv_bfloat16* Cout = y ? d_Vbh : d_Kbh;
    const float* bias = y ? bv : bk;
    if (tid < 128) bias_s[tid] = bias[tid];
    {
        const uint4* src = (const uint4*)d_WT[3 + y];
        for (int c = tid; c < 2048; c += 256) {
            int n = c >> 4, kq = c & 15;
            *(uint4*)&Ws[n * TS + kq * 8] = src[c];
        }
    }
    int rg = wid >> 1, nh = wid & 1;
    uint32_t ab0 = smem_u32(As[0]), ab1 = smem_u32(As[1]);
    uint32_t wbase = smem_u32(Ws);
    int nofs = (lane & 7) + ((lane >> 4) << 3);
    int kofs = lane & 8;
    int arow = rg * 16 + (lane & 15);
    int akof = (lane >> 4) << 3;
    int g = lane >> 2, t2 = (lane & 3) * 2;

    int tile0 = blockIdx.x * TPC;
    int tmax = NT64_NKEY - tile0; if (tmax > TPC) tmax = TPC;
    if (tmax <= 0) return;
    load_a_tile_async(ab0, d_relb, tile0, tid);
    CP_COMMIT(); CP_WAIT0();
    __syncthreads();

    for (int t = 0; t < tmax; t++) {
        uint32_t abase = (t & 1) ? ab1 : ab0;
        if (t + 1 < tmax) {
            load_a_tile_async((t & 1) ? ab0 : ab1, d_relb, tile0 + t + 1, tid);
            CP_COMMIT();
        }
        float acc[8][4];
#pragma unroll
        for (int i = 0; i < 8; i++)
#pragma unroll
            for (int j = 0; j < 4; j++) acc[i][j] = 0.f;
#pragma unroll
        for (int kc = 0; kc < 8; kc++) {
            int k0 = kc * 16;
            uint32_t a0, a1, a2, a3;
            ldsm4(a0, a1, a2, a3, abase + (uint32_t)((arow * TS + k0 + akof) * 2));
#pragma unroll
            for (int nb = 0; nb < 4; nb++) {
                uint32_t b0, b1, b2, b3;
                ldsm4(b0, b1, b2, b3, wbase +
                      (uint32_t)(((nh * 64 + nb * 16 + nofs) * TS + k0 + kofs) * 2));
                mma16816(acc[nb * 2],     a0, a1, a2, a3, b0, b1);
                mma16816(acc[nb * 2 + 1], a0, a1, a2, a3, b2, b3);
            }
        }
        int row0 = (tile0 + t) * 64 + rg * 16 + g, row1 = row0 + 8;
#pragma unroll
        for (int nc = 0; nc < 8; nc++) {
            int col = nh * 64 + nc * 8 + t2;
            float f0 = acc[nc][0] + bias_s[col];
            float f1 = acc[nc][1] + bias_s[col + 1];
            float f2 = acc[nc][2] + bias_s[col];
            float f3 = acc[nc][3] + bias_s[col + 1];
            if (row0 < NKEY)
                *(__nv_bfloat162*)(Cout + (size_t)row0 * DIM + col) =
                    __floats2bfloat162_rn(f0, f1);
            if (row1 < NKEY)
                *(__nv_bfloat162*)(Cout + (size_t)row1 * DIM + col) =
                    __floats2bfloat162_rn(f2, f3);
        }
        CP_WAIT0();
        __syncthreads();
    }
}

// ===================== CSR build ============================================
__global__ void count_all(const int* __restrict__ n0, const int* __restrict__ e0,
                          const int* __restrict__ n1, const int* __restrict__ e1,
                          const int* __restrict__ n2, const int* __restrict__ e2) {
    int mod = blockIdx.y;
    const int* nodes = (mod == 0) ? n0 : (mod == 1) ? n1 : n2;
    const int* edges = (mod == 0) ? e0 : (mod == 1) ? e1 : e2;
    int i = blockIdx.x * blockDim.x + threadIdx.x;
    if (i >= NNZV) return;
    atomicAdd(&d_ecnt[mod * EE + edges[i]], 1);
    atomicAdd(&d_ncnt[mod * NN + nodes[i]], 1);
}

__device__ __forceinline__ int wscan_incl(int v, int lane) {
#pragma unroll
    for (int o = 1; o < 32; o <<= 1) {
        int t = __shfl_up_sync(0xffffffffu, v, o);
        if (lane >= o) v += t;
    }
    return v;
}

__global__ void scan_kernel() {
    __shared__ int wsum[32];
    __shared__ int srun, stot;
    int b = blockIdx.x;
    int mod = b % 3;
    bool isE = (b < 3);
    int len = isE ? EE : NN;
    const int* cnt = isE ? (d_ecnt + mod * EE) : (d_ncnt + mod * NN);
    int* off = isE ? (d_eoff + mod * (EE + 1)) : (d_noff + mod * (NN + 1));
    int* cur = isE ? (d_ecur + mod * EE) : (d_ncur + mod * NN);
    int tid = threadIdx.x, warp = tid >> 5, lane = tid & 31;
    if (tid == 0) srun = 0;
    __syncthreads();
    for (int base = 0; base < len; base += 1024) {
        int v = (base + tid < len) ? cnt[base + tid] : 0;
        int incl = wscan_incl(v, lane);
        if (lane == 31) wsum[warp] = incl;
        __syncthreads();
        if (warp == 0) {
            int s = wsum[lane];
            int wincl = wscan_incl(s, lane);
            wsum[lane] = wincl - s;
            if (lane == 31) stot = wincl;
        }
        __syncthreads();
        int run = srun;
        int ex = run + wsum[warp] + incl - v;
        if (base + tid < len) { off[base + tid] = ex; cur[base + tid] = ex; }
        __syncthreads();
        if (tid == 0) srun = run + stot;
        __syncthreads();
    }
    if (tid == 0) off[len] = srun;
}

__global__ void scatter_all(const int* __restrict__ n0, const int* __restrict__ e0,
                            const int* __restrict__ n1, const int* __restrict__ e1,
                            const int* __restrict__ n2, const int* __restrict__ e2) {
    int mod = blockIdx.y;
    const int* nodes = (mod == 0) ? n0 : (mod == 1) ? n1 : n2;
    const int* edges = (mod == 0) ? e0 : (mod == 1) ? e1 : e2;
    int i = blockIdx.x * blockDim.x + threadIdx.x;
    if (i >= NNZV) return;
    int e = edges[i], n = nodes[i];
    int pe = atomicAdd(&d_ecur[mod * EE + e], 1);
    d_csrE[mod * NNZV + pe] = n;
    int pn = atomicAdd(&d_ncur[mod * NN + n], 1);
    d_csrN[mod * NNZV + pn] = e;
}

// ===================== small GEMM: C[50,128] = A@W + b (grid 4) =============
// Register-tiled: thread = 1 row x 8 cols; float4 smem loads; no occupancy cap
// so ptxas can pipeline (round-14 version was stalled at regs=32).
__global__ void small_nn(int mode, const float* __restrict__ Aext,
                         const float* __restrict__ W, const float* __restrict__ bias) {
    __shared__ __align__(16) float Asm[64 * DIM];    // rows >= CC zeroed
    __shared__ __align__(16) float Wsm[DIM * 32];
    float* Cout = mode ? d_att : d_qb;
    int n0 = blockIdx.x * 32;
    int tid = threadIdx.x;
    for (int i = tid; i < 64 * DIM; i += 256) {
        int q = i >> 7, k = i & 127;
        float v = 0.f;
        if (q < CC) {
            if (mode) v = d_headout[i] / d_lsum[(k >> 4) * CC + q];
            else      v = Aext[i];
        }
        Asm[i] = v;
    }
    for (int i = tid; i < DIM * 32; i += 256) {
        int k = i >> 5, c = i & 31;
        Wsm[i] = W[(size_t)k * DIM + n0 + c];
    }
    __syncthreads();
    int r = tid >> 2;                  // row 0..63
    int cq = (tid & 3) * 8;            // 8 cols per thread
    float acc[8];
#pragma unroll
    for (int c = 0; c < 8; c++) acc[c] = 0.f;
    const float4* Arow = (const float4*)&Asm[r * DIM];
#pragma unroll 4
    for (int kc = 0; kc < 32; kc++) {
        float4 a4 = Arow[kc];
#pragma unroll
        for (int j = 0; j < 4; j++) {
            int k = kc * 4 + j;
            float a = (j == 0) ? a4.x : (j == 1) ? a4.y : (j == 2) ? a4.z : a4.w;
            float4 w0 = *(const float4*)&Wsm[k * 32 + cq];
            float4 w1 = *(const float4*)&Wsm[k * 32 + cq + 4];
            acc[0] += a * w0.x; acc[1] += a * w0.y; acc[2] += a * w0.z; acc[3] += a * w0.w;
            acc[4] += a * w1.x; acc[5] += a * w1.y; acc[6] += a * w1.z; acc[7] += a * w1.w;
        }
    }
    if (r < CC) {
        float* dst = &Cout[r * DIM + n0 + cq];
#pragma unroll
        for (int c = 0; c < 8; c++) dst[c] = acc[c] + bias[n0 + cq + c];
    }
}

// ===================== hypergraph gathers (fp8 payloads) ====================
__global__ void edge_mean_kernel() {
    int gw = (blockIdx.x * blockDim.x + threadIdx.x) >> 5;
    int lane = threadIdx.x & 31;
    if (gw >= 3 * EE) return;
    int mod = gw / EE, e = gw - mod * EE;
    const int* __restrict__ base = d_csrE + mod * NNZV;
    int s0 = d_eoff[mod * (EE + 1) + e];
    int s1 = d_eoff[mod * (EE + 1) + e + 1];
    const uint32_t* __restrict__ xtm = (const uint32_t*)(d_xt8 + (size_t)mod * NN * DIM);
    float a0 = 0.f, a1 = 0.f, a2 = 0.f, a3 = 0.f;
    int j = s0;
    for (; j + 8 <= s1; j += 8) {
        int n[8];
#pragma unroll
        for (int u = 0; u < 8; u++) n[u] = base[j + u];
#pragma unroll
        for (int u = 0; u < 8; u++) {
            uint32_t p = xtm[(size_t)n[u] * 32 + lane];
            float2 f0 = e4m3x2_to_f32x2((uint16_t)(p & 0xFFFF));
            float2 f1 = e4m3x2_to_f32x2((uint16_t)(p >> 16));
            a0 += f0.x; a1 += f0.y; a2 += f1.x; a3 += f1.y;
        }
    }
    for (; j < s1; j++) {
        uint32_t p = xtm[(size_t)base[j] * 32 + lane];
        float2 f0 = e4m3x2_to_f32x2((uint16_t)(p & 0xFFFF));
        float2 f1 = e4m3x2_to_f32x2((uint16_t)(p >> 16));
        a0 += f0.x; a1 += f0.y; a2 += f1.x; a3 += f1.y;
    }
    int deg = s1 - s0; if (deg < 1) deg = 1;
    float inv = 1.f / (float)deg;
    uint16_t w0 = f32x2_to_e4m3x2(a1 * inv, a0 * inv);
    uint16_t w1 = f32x2_to_e4m3x2(a3 * inv, a2 * inv);
    ((uint32_t*)d_me8)[((size_t)mod * EE + e) * 32 + lane] =
        (uint32_t)w0 | ((uint32_t)w1 << 16);
}

__global__ void node_out_kernel(const float* __restrict__ bias_item,
                                const float* __restrict__ bias_entity,
                                const float* __restrict__ bias_word) {
    int gw = (blockIdx.x * blockDim.x + threadIdx.x) >> 5;
    int lane = threadIdx.x & 31;
    if (gw >= 3 * NN) return;
    int mod = gw / NN, n = gw - mod * NN;
    const int* __restrict__ base = d_csrN + mod * NNZV;
    int s0 = d_noff[mod * (NN + 1) + n];
    int s1 = d_noff[mod * (NN + 1) + n + 1];
    const uint32_t* __restrict__ mem = (const uint32_t*)(d_me8 + (size_t)mod * EE * DIM);
    float a0 = 0.f, a1 = 0.f, a2 = 0.f, a3 = 0.f;
    int j = s0;
    for (; j + 8 <= s1; j += 8) {
        int e8[8];
#pragma unroll
        for (int u = 0; u < 8; u++) e8[u] = base[j + u];
#pragma unroll
        for (int u = 0; u < 8; u++) {
            uint32_t p = mem[(size_t)e8[u] * 32 + lane];
            float2 f0 = e4m3x2_to_f32x2((uint16_t)(p & 0xFFFF));
            float2 f1 = e4m3x2_to_f32x2((uint16_t)(p >> 16));
            a0 += f0.x; a1 += f0.y; a2 += f1.x; a3 += f1.y;
        }
    }
    for (; j < s1; j++) {
        uint32_t p = mem[(size_t)base[j] * 32 + lane];
        float2 f0 = e4m3x2_to_f32x2((uint16_t)(p & 0xFFFF));
        float2 f1 = e4m3x2_to_f32x2((uint16_t)(p >> 16));
        a0 += f0.x; a1 += f0.y; a2 += f1.x; a3 += f1.y;
    }
    int deg = s1 - s0; if (deg < 1) deg = 1;
    float inv = 1.f / ((float)deg * FP8_SCALE);
    const float* bias = (mod == 0) ? bias_item : (mod == 1) ? bias_entity : bias_word;
    float4 bv = *(const float4*)&bias[lane * 4];
    __nv_bfloat162 b01 = __floats2bfloat162_rn(a0 * inv + bv.x, a1 * inv + bv.y);
    __nv_bfloat162 b23 = __floats2bfloat162_rn(a2 * inv + bv.z, a3 * inv + bv.w);
    uint2 o; o.x = *(uint32_t*)&b01; o.y = *(uint32_t*)&b23;
    ((uint2*)d_relb)[((size_t)mod * NN + n) * 32 + lane] = o;
}

// ===================== attention: scalar scores + mma P·V ===================
#define AT_TILES 235
#define WST 264
#define VST 264
__global__ void attn_kernel() {
    int bx = blockIdx.x;
    int h = bx / AT_TILES;
    int k0 = (bx % AT_TILES) * 256;
    int tid = threadIdx.x;
    int key = k0 + tid;
    __shared__ float qs[CC * DH];
    __shared__ __align__(16) __nv_bfloat16 wsm[64 * WST];
    __shared__ __align__(16) __nv_bfloat16 vsm[24 * VST];
    for (int i = tid; i < CC * DH; i += 256) {
        int q = i / DH, d = i % DH;
        qs[i] = d_qb[q * DIM + h * DH + d];
    }
    for (int i = tid; i < 512; i += 256) {
        int kk = i >> 1, nc = i & 1;
        __nv_bfloat16 tmp[8];
        if (k0 + kk < NKEY) {
            *(uint4*)tmp = *(const uint4*)&d_Vbh[(size_t)(k0 + kk) * DIM + h * DH + nc * 8];
        } else {
#pragma unroll
            for (int j = 0; j < 8; j++) tmp[j] = __float2bfloat16(0.f);
        }
#pragma unroll
        for (int j = 0; j < 8; j++) vsm[(nc * 8 + j) * VST + kk] = tmp[j];
    }
    {
        vsm[16 * VST + tid] = __float2bfloat16(1.f);
        __nv_bfloat16 zz = __float2bfloat16(0.f);
#pragma unroll
        for (int r = 17; r < 24; r++) vsm[r * VST + tid] = zz;
    }
    float kv[16];
    bool valid = key < NKEY;
    if (valid) {
        const __nv_bfloat16* kr = d_Kbh + (size_t)key * DIM + h * DH;
        uint4 kA = *(const uint4*)kr;
        uint4 kB = *(const uint4*)(kr + 8);
        const uint32_t* kw = (const uint32_t*)&kA;
#pragma unroll
        for (int j = 0; j < 4; j++) {
            float2 f = __bfloat1622float2(*(__nv_bfloat162*)&kw[j]);
            kv[2 * j] = f.x; kv[2 * j + 1] = f.y;
        }
        const uint32_t* kw2 = (const uint32_t*)&kB;
#pragma unroll
        for (int j = 0; j < 4; j++) {
            float2 f = __bfloat1622float2(*(__nv_bfloat162*)&kw2[j]);
            kv[8 + 2 * j] = f.x; kv[8 + 2 * j + 1] = f.y;
        }
    } else {
#pragma unroll
        for (int j = 0; j < 16; j++) kv[j] = 0.f;
    }
#pragma unroll 5
    for (int q = 0; q < CC; q++) {
        const float* qp = &qs[q * DH];
        float s = 0.f;
#pragma unroll
        for (int j = 0; j < 16; j++) s += qp[j] * kv[j];
        float w = valid ? fast_exp(s * 0.25f) : 0.f;
        wsm[q * WST + tid] = __float2bfloat16(w);
    }
    {
        __nv_bfloat16 zz = __float2bfloat16(0.f);
#pragma unroll
        for (int q = CC; q < 64; q++) wsm[q * WST + tid] = zz;
    }
    __syncthreads();
    int wid = tid >> 5, lane = tid & 31;
    int mb = wid >> 1;
    int nnb = (wid & 1) ? 1 : 2;
    int nb0 = (wid & 1) ? 2 : 0;
    uint32_t wbase = smem_u32(wsm), vbase = smem_u32(vsm);
    int ar = mb * 16 + (lane & 15), ak = (lane >> 4) << 3;
    int br = lane & 7, bk = (lane >> 3) << 3;
    float acc[2][4];
#pragma unroll
    for (int t = 0; t < 2; t++)
#pragma unroll
        for (int j = 0; j < 4; j++) acc[t][j] = 0.f;
#pragma unroll
    for (int c = 0; c < 8; c++) {
        int kc = c * 32;
        uint32_t a00, a01, a02, a03, a10, a11, a12, a13;
        ldsm4(a00, a01, a02, a03, wbase + (uint32_t)((ar * WST + kc + ak) * 2));
        ldsm4(a10, a11, a12, a13, wbase + (uint32_t)((ar * WST + kc + 16 + ak) * 2));
        for (int t = 0; t < nnb; t++) {
            int nb = nb0 + t;
            uint32_t b0, b1, b2, b3;
            ldsm4(b0, b1, b2, b3, vbase + (uint32_t)(((nb * 8 + br) * VST + kc + bk) * 2));
            mma16816(acc[t], a00, a01, a02, a03, b0, b1);
            mma16816(acc[t], a10, a11, a12, a13, b2, b3);
        }
    }
    int g = lane >> 2, t2 = (lane & 3) * 2;
    int q0 = mb * 16 + g, q1 = q0 + 8;
    for (int t = 0; t < nnb; t++) {
        int nb = nb0 + t;
        int col = nb * 8 + t2;
        if (col < 16) {
            if (q0 < CC) {
                atomicAdd(&d_headout[q0 * DIM + h * DH + col],     acc[t][0]);
                atomicAdd(&d_headout[q0 * DIM + h * DH + col + 1], acc[t][1]);
            }
            if (q1 < CC) {
                atomicAdd(&d_headout[q1 * DIM + h * DH + col],     acc[t][2]);
                atomicAdd(&d_headout[q1 * DIM + h * DH + col + 1], acc[t][3]);
            }
        } else if (col == 16) {
            if (q0 < CC) atomicAdd(&d_lsum[h * CC + q0], acc[t][0]);
            if (q1 < CC) atomicAdd(&d_lsum[h * CC + q1], acc[t][2]);
        }
    }
}

// ===================== parallel self-attn energies ==========================
__global__ void energies_kernel(const float* __restrict__ ctx,
                                const float* __restrict__ A1, const float* __restrict__ B1,
                                const float* __restrict__ A2, const float* __restrict__ B2) {
    int task = blockIdx.x;
    int d = threadIdx.x;          // 128 threads
    __shared__ float hs[DIM];
    __shared__ float red[4];
    const float* A; const float* B; const float* h; float* dst;
    if (task < CC) { h = d_att + (size_t)task * DIM; A = A1; B = B1; dst = &d_es1[task]; }
    else { h = ctx + (size_t)(task - CC) * DIM; A = A2; B = B2; dst = &d_es2[task - CC]; }
    hs[d] = h[d];
    __syncthreads();
    float acc = 0.f;
#pragma unroll 4
    for (int k = 0; k < DIM; k++) acc += hs[k] * A[(size_t)k * DIM + d];
    float v = tanhf(acc) * B[d];
#pragma unroll
    for (int o = 16; o; o >>= 1) v += __shfl_xor_sync(0xffffffffu, v, o);
    if ((d & 31) == 0) red[d >> 5] = v;
    __syncthreads();
    if (d == 0) *dst = (red[0] + red[1]) + (red[2] + red[3]);
}

// ===================== tail =================================================
__global__ void tail_kernel(const float* __restrict__ ctx,
                            const float* __restrict__ A2, const float* __restrict__ B2) {
    int d = threadIdx.x;          // 128 threads
    __shared__ float ws[64];
    __shared__ float u_s[DIM];
    __shared__ float red[4];
    __shared__ float e2u;
    if (d == 0) {
        float m = -1e30f;
        for (int r = 0; r < CC; r++) m = fmaxf(m, d_es1[r]);
        float s = 0.f;
        for (int r = 0; r < CC; r++) { float w = __expf(d_es1[r] - m); ws[r] = w; s += w; }
        float inv = 1.f / s;
        for (int r = 0; r < CC; r++) ws[r] *= inv;
    }
    __syncthreads();
    float u = 0.f;
    for (int r = 0; r < CC; r++) u += ws[r] * d_att[(size_t)r * DIM + d];
    u_s[d] = u;
    __syncthreads();
    float acc = 0.f;
#pragma unroll 4
    for (int k = 0; k < DIM; k++) acc += u_s[k] * A2[(size_t)k * DIM + d];
    float v = tanhf(acc) * B2[d];
#pragma unroll
    for (int o = 16; o; o >>= 1) v += __shfl_xor_sync(0xffffffffu, v, o);
    if ((d & 31) == 0) red[d >> 5] = v;
    __syncthreads();
    if (d == 0) {
        e2u = (red[0] + red[1]) + (red[2] + red[3]);
        float m = e2u;
        for (int r = 0; r < CC; r++) m = fmaxf(m, d_es2[r]);
        float s = 0.f;
        for (int r = 0; r < CC; r++) { float w = __expf(d_es2[r] - m); ws[r] = w; s += w; }
        float wu = __expf(e2u - m); ws[CC] = wu; s += wu;
        float inv = 1.f / s;
        for (int r = 0; r <= CC; r++) ws[r] *= inv;
    }
    __syncthreads();
    float o = 0.f;
    for (int r = 0; r < CC; r++) o += ws[r] * ctx[(size_t)r * DIM + d];
    o += ws[CC] * u_s[d];
    d_urepr[d] = o;
}

// ===================== final scores =========================================
__global__ void recscore_kernel(const float* __restrict__ W,
                                const float* __restrict__ b,
                                float* __restrict__ out) {
    __shared__ float us[DIM];
    int tid = threadIdx.x;
    if (tid < DIM) us[tid] = d_urepr[tid];
    __syncthreads();
    int j = blockIdx.x * 256 + tid;
    if (j >= NENT) return;
    float a0 = 0.f, a1 = 0.f, a2 = 0.f, a3 = 0.f;
#pragma unroll
    for (int d = 0; d < DIM; d += 4) {
        a0 += us[d + 0] * W[(size_t)(d + 0) * NENT + j];
        a1 += us[d + 1] * W[(size_t)(d + 1) * NENT + j];
        a2 += us[d + 2] * W[(size_t)(d + 2) * NENT + j];
        a3 += us[d + 3] * W[(size_t)(d + 3) * NENT + j];
    }
    out[j] = (a0 + a1) + (a2 + a3) + b[j];
}

// ===================== launch ===============================================
extern "C" void kernel_launch(void* const* d_in, const int* in_sizes, int n_in,
                              void* d_out, int out_size) {
    const float* item_emb     = (const float*)d_in[0];
    const float* entity_emb   = (const float*)d_in[1];
    const float* word_emb     = (const float*)d_in[2];
    const float* context_ent  = (const float*)d_in[3];
    const float* theta_item   = (const float*)d_in[4];
    const float* bias_item    = (const float*)d_in[5];
    const float* theta_entity = (const float*)d_in[6];
    const float* bias_entity  = (const float*)d_in[7];
    const float* theta_word   = (const float*)d_in[8];
    const float* bias_word    = (const float*)d_in[9];
    const float* Wq = (const float*)d_in[10];  const float* bq = (const float*)d_in[11];
    const float* Wk = (const float*)d_in[12];  const float* bk = (const float*)d_in[13];
    const float* Wv = (const float*)d_in[14];  const float* bv = (const float*)d_in[15];
    const float* Wo = (const float*)d_in[16];  const float* bo = (const float*)d_in[17];
    const float* a_his = (const float*)d_in[18]; const float* b_his = (const float*)d_in[19];
    const float* a_kg  = (const float*)d_in[20]; const float* b_kg  = (const float*)d_in[21];
    const float* rec_W = (const float*)d_in[22]; const float* rec_b = (const float*)d_in[23];
    const int* item_nodes   = (const int*)d_in[24];
    const int* item_edges   = (const int*)d_in[25];
    const int* entity_nodes = (const int*)d_in[26];
    const int* entity_edges = (const int*)d_in[27];
    const int* word_nodes   = (const int*)d_in[28];
    const int* word_edges   = (const int*)d_in[29];
    float* out = (float*)d_out;

    zero_kernel<<<(3 * NN + 255) / 256, 256>>>();

    convW_kernel<<<dim3(5, 8), 128>>>(theta_item, theta_entity, theta_word, Wk, Wv);
    convA_kernel<<<(3 * NN_PAD * 16 + 127) / 128, 128>>>(item_emb, entity_emb, word_emb);

    // Q projection (register-tiled small GEMM)
    small_nn<<<4, 256>>>(0, context_ent, Wq, bq);

    // xt GEMMs
    mmagemm_x<<<dim3((NT64_NN + TPCX - 1) / TPCX, 3), 256>>>();

    // CSR build
    dim3 cgrid((NNZV + 255) / 256, 3);
    count_all<<<cgrid, 256>>>(item_nodes, item_edges, entity_nodes, entity_edges,
                              word_nodes, word_edges);
    scan_kernel<<<6, 1024>>>();
    scatter_all<<<cgrid, 256>>>(item_nodes, item_edges, entity_nodes, entity_edges,
                                word_nodes, word_edges);

    // hypergraph aggregation
    edge_mean_kernel<<<(3 * EE + 7) / 8, 256>>>();
    node_out_kernel<<<(3 * NN + 7) / 8, 256>>>(bias_item, bias_entity, bias_word);

    // K and V projections
    mmagemm_kv<<<dim3((NT64_NKEY + TPC - 1) / TPC, 2), 256>>>(bk, bv);

    // attention
    attn_kernel<<<NHEAD * AT_TILES, 256>>>();

    // Wo (register-tiled small GEMM, fused normalization)
    small_nn<<<4, 256>>>(1, nullptr, Wo, bo);

    // parallel energies + tail
    energies_kernel<<<2 * CC, 128>>>(context_ent, a_his, b_his, a_kg, b_kg);
    tail_kernel<<<1, 128>>>(context_ent, a_kg, b_kg);

    // final scores
    recscore_kernel<<<(NENT + 255) / 256, 256>>>(rec_W, rec_b, out);
}